// round 8
// baseline (speedup 1.0000x reference)
#include <cuda_runtime.h>
#include <cuda_bf16.h>
#include <cstdint>

#define BSZ 16
#define SEQ 2048
#define DKE 64
#define KR_ROWS 2176

// -------- device-global bf16 split scratch --------
__device__ __align__(16) __nv_bfloat16 g_qhi[BSZ * SEQ * DKE];
__device__ __align__(16) __nv_bfloat16 g_qlo[BSZ * SEQ * DKE];
__device__ __align__(16) __nv_bfloat16 g_khi[BSZ * SEQ * DKE];
__device__ __align__(16) __nv_bfloat16 g_klo[BSZ * SEQ * DKE];
__device__ __align__(16) __nv_bfloat16 g_vthi[BSZ * DKE * SEQ];  // [b][d][t]
__device__ __align__(16) __nv_bfloat16 g_vtlo[BSZ * DKE * SEQ];
__device__ __align__(16) __nv_bfloat16 g_krthi[KR_ROWS * DKE];   // [c][d], c>=SEQ zero

__device__ __forceinline__ uint32_t smem_to_u32(const void* p) {
    uint32_t a;
    asm("{ .reg .u64 t; cvta.to.shared.u64 t, %1; cvt.u32.u64 %0, t; }" : "=r"(a) : "l"(p));
    return a;
}

#define LDSM4(r0, r1, r2, r3, addr) \
    asm volatile("ldmatrix.sync.aligned.m8n8.x4.shared.b16 {%0,%1,%2,%3}, [%4];" \
                 : "=r"(r0), "=r"(r1), "=r"(r2), "=r"(r3) : "r"(addr))

#define MMA16816(d, a, bb0, bb1) \
    asm volatile("mma.sync.aligned.m16n8k16.row.col.f32.bf16.bf16.f32 " \
                 "{%0,%1,%2,%3},{%4,%5,%6,%7},{%8,%9},{%0,%1,%2,%3};" \
                 : "+f"((d)[0]), "+f"((d)[1]), "+f"((d)[2]), "+f"((d)[3]) \
                 : "r"((a)[0]), "r"((a)[1]), "r"((a)[2]), "r"((a)[3]), "r"(bb0), "r"(bb1))

#define CP16(dst, src) \
    asm volatile("cp.async.ca.shared.global [%0], [%1], 16;" :: "r"(dst), "l"(src))
#define CP_COMMIT() asm volatile("cp.async.commit_group;")
#define CP_WAIT0()  asm volatile("cp.async.wait_group 0;")
#define CP_WAIT1()  asm volatile("cp.async.wait_group 1;")

#define C_SCALE 0.1803368801111204f  /* log2(e)/sqrt(64) */

__device__ __forceinline__ float fexp2(float x) {
    x = fmaxf(x, -126.0f);
    float n = rintf(x), f = x - n;
    float r = 0.00133335581464f;
    r = fmaf(r, f, 0.00961812910763f);
    r = fmaf(r, f, 0.0555041086648f);
    r = fmaf(r, f, 0.2402265069591f);
    r = fmaf(r, f, 0.69314718056f);
    r = fmaf(r, f, 1.0f);
    return r * __int_as_float(((int)n + 127) << 23);
}

// -------- merged prologue: 3208 blocks x 256 threads --------
__global__ void prologue_kernel(const float* __restrict__ Q, const float* __restrict__ K,
                                const float* __restrict__ V, const float* __restrict__ Kr) {
    __shared__ float tile[32][33];
    const int bx = blockIdx.x, tid = threadIdx.x;
    if (bx < 1024) {
        const bool isQ = bx < 512;
        const float* src = isQ ? Q : K;
        __nv_bfloat16* hi = isQ ? g_qhi : g_khi;
        __nv_bfloat16* lo = isQ ? g_qlo : g_klo;
        const int base = (bx & 511) * 4096 + tid * 4;
        #pragma unroll
        for (int k = 0; k < 4; k++) {
            int i = base + k * 1024;
            float4 x = *(const float4*)(src + i);
            __nv_bfloat162 h0 = __float22bfloat162_rn(make_float2(x.x, x.y));
            __nv_bfloat162 h1 = __float22bfloat162_rn(make_float2(x.z, x.w));
            *(__nv_bfloat162*)(hi + i) = h0;
            *(__nv_bfloat162*)(hi + i + 2) = h1;
            __nv_bfloat162 l0 = __float22bfloat162_rn(make_float2(
                x.x - __bfloat162float(h0.x), x.y - __bfloat162float(h0.y)));
            __nv_bfloat162 l1 = __float22bfloat162_rn(make_float2(
                x.z - __bfloat162float(h1.x), x.w - __bfloat162float(h1.y)));
            *(__nv_bfloat162*)(lo + i) = l0;
            *(__nv_bfloat162*)(lo + i + 2) = l1;
        }
    } else if (bx < 3072) {
        const int v = bx - 1024;
        const int b = v >> 7, s0 = (v & 63) * 32, d0 = ((v >> 6) & 1) * 32;
        const int tx = tid & 31, ty = tid >> 5;
        const float* ip = V + (size_t)b * SEQ * DKE;
        for (int i = ty; i < 32; i += 8) tile[i][tx] = ip[(size_t)(s0 + i) * DKE + d0 + tx];
        __syncthreads();
        for (int i = ty; i < 32; i += 8) {
            float x = tile[tx][i];
            __nv_bfloat16 h = __float2bfloat16(x);
            size_t oi = ((size_t)b * DKE + d0 + i) * SEQ + s0 + tx;
            g_vthi[oi] = h;
            g_vtlo[oi] = __float2bfloat16(x - __bfloat162float(h));
        }
    } else {
        const int r = bx - 3072;
        const int c0 = (r % 68) * 32, d0 = (r / 68) * 32;
        const int tx = tid & 31, ty = tid >> 5;
        for (int i = ty; i < 32; i += 8) {
            int c = c0 + tx;
            tile[i][tx] = (c < SEQ) ? Kr[(size_t)(d0 + i) * SEQ + c] : 0.0f;
        }
        __syncthreads();
        for (int i = ty; i < 32; i += 8)
            g_krthi[(size_t)(c0 + i) * DKE + d0 + tx] = __float2bfloat16(tile[tx][i]);
    }
}

// -------- smem layout (bytes) --------
#define KHI_O 0            /* 128 rows x 144B */
#define KLO_O 18432
#define KR_O  36864        /* 256 rows x 144B */
#define VHI_O 73728        /* 64 rows x 272B */
#define VLO_O 91136
#define BS_O  108544       /* f32 128 x 132 */
#define SMEM_TOTAL 176128

__device__ __forceinline__ void issue_K(uint32_t sm, int b, int t0, int tid) {
    for (int i = tid; i < 1024; i += 256) {
        int r = i >> 3, c = i & 7;
        CP16(sm + KHI_O + r * 144 + c * 16,
             (const char*)(g_khi + ((size_t)b * SEQ + t0 + r) * DKE + c * 8));
        CP16(sm + KLO_O + r * 144 + c * 16,
             (const char*)(g_klo + ((size_t)b * SEQ + t0 + r) * DKE + c * 8));
    }
    CP_COMMIT();
}
__device__ __forceinline__ void issue_KR(uint32_t sm, int c_base, int tid) {
    for (int i = tid; i < 2048; i += 256) {
        int r = i >> 3, c = i & 7;
        CP16(sm + KR_O + r * 144 + c * 16,
             (const char*)(g_krthi + (size_t)(c_base + r) * DKE + c * 8));
    }
    CP_COMMIT();
}
__device__ __forceinline__ void issue_V(uint32_t sm, int b, int t0, int tid) {
    for (int i = tid; i < 1024; i += 256) {
        int d = i >> 4, c = i & 15;
        size_t src = ((size_t)b * DKE + d) * SEQ + t0 + c * 8;
        CP16(sm + VHI_O + d * 272 + c * 16, (const char*)(g_vthi + src));
        CP16(sm + VLO_O + d * 272 + c * 16, (const char*)(g_vtlo + src));
    }
    CP_COMMIT();
}

__global__ __launch_bounds__(256, 1)
void attn_mma_kernel(float* __restrict__ out) {
    extern __shared__ char smem[];
    const uint32_t sm = smem_to_u32(smem);
    const int tid = threadIdx.x, w = tid >> 5, l = tid & 31;
    const int g = l >> 2, tg = l & 3;
    const int R = w * 16;
    const int ua = R + g, ub = R + g + 8;
    const int b = blockIdx.y;
    const int u0 = (15 - (int)blockIdx.x) * 128;  // big tiles first

    // ---- stage Q hi/lo into K buffers, build persistent Q fragments ----
    for (int i = tid; i < 1024; i += 256) {
        int r = i >> 3, c = i & 7;
        CP16(sm + KHI_O + r * 144 + c * 16,
             (const char*)(g_qhi + ((size_t)b * SEQ + u0 + r) * DKE + c * 8));
        CP16(sm + KLO_O + r * 144 + c * 16,
             (const char*)(g_qlo + ((size_t)b * SEQ + u0 + r) * DKE + c * 8));
    }
    CP_COMMIT();
    CP_WAIT0();
    __syncthreads();

    uint32_t qh[4][4], ql[4][4];
    {
        const int qrow = R + (l & 15);
        const int qko = ((l >> 4) & 1) * 8;
        #pragma unroll
        for (int c = 0; c < 4; c++) {
            uint32_t off = (uint32_t)(qrow * 144 + (c * 16 + qko) * 2);
            LDSM4(qh[c][0], qh[c][1], qh[c][2], qh[c][3], sm + KHI_O + off);
            LDSM4(ql[c][0], ql[c][1], ql[c][2], ql[c][3], sm + KLO_O + off);
        }
    }
    __syncthreads();  // Q fragments extracted by all warps before K(0) overwrites

    const int nIter = u0 / 128 + 1;
    // pipeline prologue: K(0), KR(0)
    issue_K(sm, b, 0, tid);
    issue_KR(sm, 1920 - u0, tid);

    const int brow = l & 7;
    const int bko = (l >> 3) * 8;
    float* Bs = (float*)(smem + BS_O);

    float m_a = -1e30f, m_b = -1e30f, l_a = 0.0f, l_b = 0.0f;
    float o[8][4];
    #pragma unroll
    for (int j = 0; j < 8; j++) { o[j][0] = o[j][1] = o[j][2] = o[j][3] = 0.0f; }

    for (int it = 0; it < nIter; ++it) {
        const int t0 = it * 128;
        const int t0n = (it + 1 < nIter) ? t0 + 128 : t0;  // clamped next tile

        // K(it) ready? (pending: K(it), KR(it))
        CP_WAIT1();
        __syncthreads();
        issue_V(sm, b, t0, tid);

        // ---- S = Q K^T, 3 error-compensated passes ----
        float s[16][4];
        #pragma unroll
        for (int j = 0; j < 16; j++) {
            uint32_t bh[8], bl[8];
            uint32_t ab = (uint32_t)((8 * j + brow) * 144 + bko * 2);
            LDSM4(bh[0], bh[1], bh[2], bh[3], sm + KHI_O + ab);
            LDSM4(bh[4], bh[5], bh[6], bh[7], sm + KHI_O + ab + 64);
            LDSM4(bl[0], bl[1], bl[2], bl[3], sm + KLO_O + ab);
            LDSM4(bl[4], bl[5], bl[6], bl[7], sm + KLO_O + ab + 64);
            float* d = s[j];
            d[0] = d[1] = d[2] = d[3] = 0.0f;
            #pragma unroll
            for (int c = 0; c < 4; c++) {
                MMA16816(d, qh[c], bh[2 * c], bh[2 * c + 1]);
                MMA16816(d, qh[c], bl[2 * c], bl[2 * c + 1]);
                MMA16816(d, ql[c], bh[2 * c], bh[2 * c + 1]);
            }
        }

        // KR(it) ready? (pending: KR(it), V(it))
        CP_WAIT1();
        __syncthreads();
        issue_K(sm, b, t0n, tid);

        // ---- bias GEMM (Qhi only) on this warp's 18 window tiles + shift scatter ----
        {
            const int j0 = 14 - 2 * w;
            #pragma unroll
            for (int jj = 0; jj < 18; jj++) {
                int j = j0 + jj;
                uint32_t kb[8];
                uint32_t ab = (uint32_t)((8 * j + brow) * 144 + bko * 2);
                LDSM4(kb[0], kb[1], kb[2], kb[3], sm + KR_O + ab);
                LDSM4(kb[4], kb[5], kb[6], kb[7], sm + KR_O + ab + 64);
                float d[4] = {0.0f, 0.0f, 0.0f, 0.0f};
                #pragma unroll
                for (int c = 0; c < 4; c++)
                    MMA16816(d, qh[c], kb[2 * c], kb[2 * c + 1]);
                int cc = 8 * j + 2 * tg;
                int ta = cc + ua - 127, tb = cc + ub - 127;
                if ((unsigned)ta < 128u)       Bs[ua * 132 + ta] = d[0];
                if ((unsigned)(ta + 1) < 128u) Bs[ua * 132 + ta + 1] = d[1];
                if ((unsigned)tb < 128u)       Bs[ub * 132 + tb] = d[2];
                if ((unsigned)(tb + 1) < 128u) Bs[ub * 132 + tb + 1] = d[3];
            }
        }

        // V(it) ready? (pending: V(it), K(it+1))
        CP_WAIT1();
        __syncthreads();
        issue_KR(sm, 1920 - u0 + t0n, tid);

        // ---- logits + online softmax ----
        #pragma unroll
        for (int j = 0; j < 16; j++) {
            int cc = 8 * j + 2 * tg;
            float2 ba = *(float2*)&Bs[ua * 132 + cc];
            float2 bb = *(float2*)&Bs[ub * 132 + cc];
            s[j][0] = (s[j][0] + ba.x) * C_SCALE;
            s[j][1] = (s[j][1] + ba.y) * C_SCALE;
            s[j][2] = (s[j][2] + bb.x) * C_SCALE;
            s[j][3] = (s[j][3] + bb.y) * C_SCALE;
        }
        if (t0 == u0) {
            #pragma unroll
            for (int j = 0; j < 16; j++) {
                int cc = 8 * j + 2 * tg;
                if (cc > ua)     s[j][0] = -1e30f;
                if (cc + 1 > ua) s[j][1] = -1e30f;
                if (cc > ub)     s[j][2] = -1e30f;
                if (cc + 1 > ub) s[j][3] = -1e30f;
            }
        }
        float ma = -1e30f, mb = -1e30f;
        #pragma unroll
        for (int j = 0; j < 16; j++) {
            ma = fmaxf(ma, fmaxf(s[j][0], s[j][1]));
            mb = fmaxf(mb, fmaxf(s[j][2], s[j][3]));
        }
        ma = fmaxf(ma, __shfl_xor_sync(0xffffffffu, ma, 1));
        ma = fmaxf(ma, __shfl_xor_sync(0xffffffffu, ma, 2));
        mb = fmaxf(mb, __shfl_xor_sync(0xffffffffu, mb, 1));
        mb = fmaxf(mb, __shfl_xor_sync(0xffffffffu, mb, 2));
        const float mna = fmaxf(m_a, ma), mnb = fmaxf(m_b, mb);
        const float alfa = fexp2(m_a - mna), alfb = fexp2(m_b - mnb);
        m_a = mna; m_b = mnb;
        float pa = 0.0f, pb = 0.0f;
        #pragma unroll
        for (int j = 0; j < 16; j++) {
            s[j][0] = fexp2(s[j][0] - mna);
            s[j][1] = fexp2(s[j][1] - mna);
            s[j][2] = fexp2(s[j][2] - mnb);
            s[j][3] = fexp2(s[j][3] - mnb);
            pa += s[j][0] + s[j][1];
            pb += s[j][2] + s[j][3];
        }
        pa += __shfl_xor_sync(0xffffffffu, pa, 1);
        pa += __shfl_xor_sync(0xffffffffu, pa, 2);
        pb += __shfl_xor_sync(0xffffffffu, pb, 1);
        pb += __shfl_xor_sync(0xffffffffu, pb, 2);
        l_a = l_a * alfa + pa;
        l_b = l_b * alfb + pb;
        #pragma unroll
        for (int j = 0; j < 8; j++) {
            o[j][0] *= alfa; o[j][1] *= alfa;
            o[j][2] *= alfb; o[j][3] *= alfb;
        }

        // ---- P -> bf16 hi/lo A-fragments ----
        uint32_t ph[16][2], pl[16][2];
        #pragma unroll
        for (int j = 0; j < 16; j++) {
            __nv_bfloat162 h0 = __float22bfloat162_rn(make_float2(s[j][0], s[j][1]));
            __nv_bfloat162 h1 = __float22bfloat162_rn(make_float2(s[j][2], s[j][3]));
            ph[j][0] = *(uint32_t*)&h0;
            ph[j][1] = *(uint32_t*)&h1;
            __nv_bfloat162 l0 = __float22bfloat162_rn(make_float2(
                s[j][0] - __bfloat162float(h0.x), s[j][1] - __bfloat162float(h0.y)));
            __nv_bfloat162 l1 = __float22bfloat162_rn(make_float2(
                s[j][2] - __bfloat162float(h1.x), s[j][3] - __bfloat162float(h1.y)));
            pl[j][0] = *(uint32_t*)&l0;
            pl[j][1] = *(uint32_t*)&l1;
        }

        // ---- O += P V, 3 error-compensated passes ----
        #pragma unroll
        for (int jd = 0; jd < 8; jd++) {
            uint32_t vh[16], vl[16];
            uint32_t vb = (uint32_t)((8 * jd + brow) * 272 + bko * 2);
            LDSM4(vh[0], vh[1], vh[2], vh[3], sm + VHI_O + vb);
            LDSM4(vh[4], vh[5], vh[6], vh[7], sm + VHI_O + vb + 64);
            LDSM4(vh[8], vh[9], vh[10], vh[11], sm + VHI_O + vb + 128);
            LDSM4(vh[12], vh[13], vh[14], vh[15], sm + VHI_O + vb + 192);
            LDSM4(vl[0], vl[1], vl[2], vl[3], sm + VLO_O + vb);
            LDSM4(vl[4], vl[5], vl[6], vl[7], sm + VLO_O + vb + 64);
            LDSM4(vl[8], vl[9], vl[10], vl[11], sm + VLO_O + vb + 128);
            LDSM4(vl[12], vl[13], vl[14], vl[15], sm + VLO_O + vb + 192);
            float* d = o[jd];
            #pragma unroll
            for (int c = 0; c < 8; c++) {
                uint32_t a[4] = {ph[2 * c][0], ph[2 * c][1], ph[2 * c + 1][0], ph[2 * c + 1][1]};
                uint32_t al[4] = {pl[2 * c][0], pl[2 * c][1], pl[2 * c + 1][0], pl[2 * c + 1][1]};
                MMA16816(d, a, vh[2 * c], vh[2 * c + 1]);
                MMA16816(d, a, vl[2 * c], vl[2 * c + 1]);
                MMA16816(d, al, vh[2 * c], vh[2 * c + 1]);
            }
        }
    }

    // ---- epilogue ----
    const float inva = 1.0f / l_a, invb = 1.0f / l_b;
    float* orow_a = out + ((size_t)b * SEQ + u0 + ua) * DKE;
    float* orow_b = out + ((size_t)b * SEQ + u0 + ub) * DKE;
    #pragma unroll
    for (int jd = 0; jd < 8; jd++) {
        int cc = 8 * jd + 2 * tg;
        float2 ra, rb;
        ra.x = o[jd][0] * inva; ra.y = o[jd][1] * inva;
        rb.x = o[jd][2] * invb; rb.y = o[jd][3] * invb;
        *(float2*)(orow_a + cc) = ra;
        *(float2*)(orow_b + cc) = rb;
    }
    CP_WAIT0();  // drain trailing prefetches before exit
}

extern "C" void kernel_launch(void* const* d_in, const int* in_sizes, int n_in,
                              void* d_out, int out_size) {
    const float* Q  = (const float*)d_in[0];
    const float* K  = (const float*)d_in[1];
    const float* V  = (const float*)d_in[2];
    const float* Kr = (const float*)d_in[3];
    float* out = (float*)d_out;

    cudaFuncSetAttribute(attn_mma_kernel, cudaFuncAttributeMaxDynamicSharedMemorySize, SMEM_TOTAL);

    prologue_kernel<<<3208, 256>>>(Q, K, V, Kr);
    attn_mma_kernel<<<dim3(16, BSZ), 256, SMEM_TOTAL>>>(out);
}